// round 10
// baseline (speedup 1.0000x reference)
#include <cuda_runtime.h>

#define N_NODES 50000
#define D 128
#define NHEAD 8
#define HD 16
#define E_EDGES 800000
#define EDGE_DIM 4
#define EPS_GN 1e-5f

// ---------------- scratch (static device allocations; no cudaMalloc) -------
__device__ float g_q[N_NODES * D];
__device__ float g_k[N_NODES * D];
__device__ float g_v[N_NODES * D];
__device__ float g_agg[N_NODES * D];
__device__ float g_o[N_NODES * D];
__device__ int   g_deg[N_NODES];
__device__ int   g_rowstart[N_NODES + 1];
__device__ int   g_cursor[N_NODES];
__device__ int   g_csr[E_EDGES];
__device__ int   g_mode64;      // 1 if edge_index is int64, 0 if int32
__device__ int   g_nonzero_odd; // detection scratch

// index loader: pos in [0, 2E). Handles int32 or int64 storage.
__device__ __forceinline__ int load_idx(const void* ei, int pos, int mode64) {
    long long v;
    if (mode64) v = ((const long long*)ei)[pos];
    else        v = ((const int*)ei)[pos];
    int i = (int)v;
    // clamp for safety: bad index -> wrong answer, not a trap
    return (i < 0) ? 0 : (i >= N_NODES ? N_NODES - 1 : i);
}

// ---------------- dtype detection ------------------------------------------
// For int64 little-endian data with values < 2^31, every odd 32-bit word of
// the src region is 0. For int32 data the odd words are random node ids.
__global__ void k_detect(const int* __restrict__ ei_w) {
    int t = threadIdx.x;
    if (t == 0) g_nonzero_odd = 0;
    __syncthreads();
    if (t < 64) {
        if (ei_w[2 * t + 1] != 0) atomicOr(&g_nonzero_odd, 1);
    }
    __syncthreads();
    if (t == 0) g_mode64 = (g_nonzero_odd == 0) ? 1 : 0;
}

// ---------------- CSR build ------------------------------------------------
__global__ void k_zero() {
    int i = blockIdx.x * blockDim.x + threadIdx.x;
    if (i < N_NODES) { g_deg[i] = 0; g_cursor[i] = 0; }
}

__global__ void k_hist(const void* __restrict__ ei) {
    int m64 = g_mode64;
    for (int e = blockIdx.x * blockDim.x + threadIdx.x; e < E_EDGES;
         e += gridDim.x * blockDim.x) {
        int dst = load_idx(ei, E_EDGES + e, m64);
        atomicAdd(&g_deg[dst], 1);
    }
}

// single-block exclusive scan over g_deg -> g_rowstart (N=50000, 49 passes)
__global__ void k_scan() {
    __shared__ int warp_sums[32];
    __shared__ int s_carry;
    int tid = threadIdx.x;
    if (tid == 0) s_carry = 0;
    __syncthreads();
    for (int base = 0; base < N_NODES; base += 1024) {
        int i = base + tid;
        int v = (i < N_NODES) ? g_deg[i] : 0;
        int x = v;
        #pragma unroll
        for (int off = 1; off < 32; off *= 2) {
            int y = __shfl_up_sync(0xffffffffu, x, off);
            if ((tid & 31) >= off) x += y;
        }
        if ((tid & 31) == 31) warp_sums[tid >> 5] = x;
        __syncthreads();
        if (tid < 32) {
            int w = warp_sums[tid];
            #pragma unroll
            for (int off = 1; off < 32; off *= 2) {
                int y = __shfl_up_sync(0xffffffffu, w, off);
                if (tid >= off) w += y;
            }
            warp_sums[tid] = w;
        }
        __syncthreads();
        int incl = x + ((tid >= 32) ? warp_sums[(tid >> 5) - 1] : 0);
        if (i < N_NODES) g_rowstart[i] = s_carry + incl - v;
        int total = warp_sums[31];
        __syncthreads();
        if (tid == 0) s_carry += total;
        __syncthreads();
    }
    if (tid == 0) g_rowstart[N_NODES] = s_carry;
}

__global__ void k_scatter(const void* __restrict__ ei) {
    int m64 = g_mode64;
    for (int e = blockIdx.x * blockDim.x + threadIdx.x; e < E_EDGES;
         e += gridDim.x * blockDim.x) {
        int dst = load_idx(ei, E_EDGES + e, m64);
        int pos = atomicAdd(&g_cursor[dst], 1);
        g_csr[g_rowstart[dst] + pos] = e;
    }
}

// ---------------- fp32 tiled GEMM: C[M,128] = X[M,128] @ W[128,128] + b ----
// BM=64, BN=64, BK=16, 256 threads, each thread 4x4 outputs.
__device__ __forceinline__ void gemm_body(const float* __restrict__ X,
                                          const float* __restrict__ W,
                                          const float* __restrict__ bias,
                                          float* __restrict__ C, int M) {
    __shared__ __align__(16) float xs[16][68];  // [kk][row]
    __shared__ __align__(16) float ws[16][68];  // [kk][col]
    int tid = threadIdx.x;
    int tx = tid & 15, ty = tid >> 4;
    int rowBase = blockIdx.x * 64;
    int colBase = blockIdx.y * 64;

    float acc[4][4];
    #pragma unroll
    for (int i = 0; i < 4; i++)
        #pragma unroll
        for (int j = 0; j < 4; j++) acc[i][j] = 0.f;

    int lr = tid & 3;       // which k-quad of the x row
    int lrow = tid >> 2;    // 0..63
    int wc = (tid & 15) * 4;
    int wk = tid >> 4;

    for (int k0 = 0; k0 < 128; k0 += 16) {
        int gr = rowBase + lrow;
        float4 xv = make_float4(0.f, 0.f, 0.f, 0.f);
        if (gr < M) xv = *(const float4*)&X[gr * 128 + k0 + lr * 4];
        xs[lr * 4 + 0][lrow] = xv.x;
        xs[lr * 4 + 1][lrow] = xv.y;
        xs[lr * 4 + 2][lrow] = xv.z;
        xs[lr * 4 + 3][lrow] = xv.w;

        float4 wv = *(const float4*)&W[(k0 + wk) * 128 + colBase + wc];
        *(float4*)&ws[wk][wc] = wv;
        __syncthreads();

        #pragma unroll
        for (int kk = 0; kk < 16; ++kk) {
            float4 a = *(const float4*)&xs[kk][ty * 4];
            float4 b = *(const float4*)&ws[kk][tx * 4];
            float av[4] = {a.x, a.y, a.z, a.w};
            float bv[4] = {b.x, b.y, b.z, b.w};
            #pragma unroll
            for (int i = 0; i < 4; i++)
                #pragma unroll
                for (int j = 0; j < 4; j++) acc[i][j] += av[i] * bv[j];
        }
        __syncthreads();
    }

    float4 b4 = *(const float4*)&bias[colBase + tx * 4];
    #pragma unroll
    for (int i = 0; i < 4; i++) {
        int r = rowBase + ty * 4 + i;
        if (r < M) {
            float4 ob;
            ob.x = acc[i][0] + b4.x;
            ob.y = acc[i][1] + b4.y;
            ob.z = acc[i][2] + b4.z;
            ob.w = acc[i][3] + b4.w;
            *(float4*)&C[r * 128 + colBase + tx * 4] = ob;
        }
    }
}

// QKV in one launch: blockIdx.z selects (W, b, out)
__global__ void __launch_bounds__(256) k_gemm_qkv(const float* __restrict__ X,
                                                  const float* __restrict__ Wq,
                                                  const float* __restrict__ bq,
                                                  const float* __restrict__ Wk,
                                                  const float* __restrict__ bk,
                                                  const float* __restrict__ Wv,
                                                  const float* __restrict__ bv) {
    const float* W;
    const float* b;
    float* C;
    if (blockIdx.z == 0)      { W = Wq; b = bq; C = g_q; }
    else if (blockIdx.z == 1) { W = Wk; b = bk; C = g_k; }
    else                      { W = Wv; b = bv; C = g_v; }
    gemm_body(X, W, b, C, N_NODES);
}

// O projection: X = g_agg (device global), out = g_o
__global__ void __launch_bounds__(256) k_gemm_o(const float* __restrict__ Wo,
                                                const float* __restrict__ bo) {
    gemm_body(g_agg, Wo, bo, g_o, N_NODES);
}

// ---------------- fused edge logits + online scatter-softmax + aggregation -
// one warp per dst node; lane l owns channels 4l..4l+3 (head = l/4)
__global__ void __launch_bounds__(512) k_agg(const void* __restrict__ ei,
                                             const float* __restrict__ ea,
                                             const float* __restrict__ We,
                                             const float* __restrict__ be) {
    int gw = (blockIdx.x * blockDim.x + threadIdx.x) >> 5;
    int lane = threadIdx.x & 31;
    if (gw >= N_NODES) return;
    int m64 = g_mode64;
    int n = gw;
    int rs = g_rowstart[n];
    int re = g_rowstart[n + 1];
    int h = lane >> 2;

    float4 ql = *(const float4*)&g_q[n * D + lane * 4];
    float w0 = We[0 * NHEAD + h], w1 = We[1 * NHEAD + h];
    float w2 = We[2 * NHEAD + h], w3 = We[3 * NHEAD + h];
    float beh = be[h];

    float m = -1e30f, ssum = 0.f;
    float acc0 = 0.f, acc1 = 0.f, acc2 = 0.f, acc3 = 0.f;

    for (int j = rs; j < re; ++j) {
        int e = g_csr[j];
        int s = load_idx(ei, e, m64);            // src node
        const float4 kv = *(const float4*)&g_k[s * D + lane * 4];
        float p = ql.x * kv.x + ql.y * kv.y + ql.z * kv.z + ql.w * kv.w;
        p += __shfl_xor_sync(0xffffffffu, p, 1);
        p += __shfl_xor_sync(0xffffffffu, p, 2);  // full per-head dot in quad
        float4 ea4 = *(const float4*)&ea[e * 4];
        float logit = p * 0.25f +
                      (ea4.x * w0 + ea4.y * w1 + ea4.z * w2 + ea4.w * w3 + beh);
        float mn = fmaxf(m, logit);
        float f = __expf(m - mn);
        float w = __expf(logit - mn);
        ssum = ssum * f + w;
        const float4 vv = *(const float4*)&g_v[s * D + lane * 4];
        acc0 = acc0 * f + w * vv.x;
        acc1 = acc1 * f + w * vv.y;
        acc2 = acc2 * f + w * vv.z;
        acc3 = acc3 * f + w * vv.w;
        m = mn;
    }
    float inv = 1.0f / fmaxf(ssum, 1e-6f);
    float4 o;
    o.x = acc0 * inv; o.y = acc1 * inv; o.z = acc2 * inv; o.w = acc3 * inv;
    *(float4*)&g_agg[n * D + lane * 4] = o;
}

// ---------------- GroupNorm (8 groups of 16 ch): warp per row --------------
__global__ void __launch_bounds__(512) k_gn(const float* __restrict__ gamma,
                                            const float* __restrict__ beta,
                                            float* __restrict__ out) {
    int gw = (blockIdx.x * blockDim.x + threadIdx.x) >> 5;
    int lane = threadIdx.x & 31;
    if (gw >= N_NODES) return;
    float4 y = *(const float4*)&g_o[gw * 128 + lane * 4];
    float s = y.x + y.y + y.z + y.w;
    s += __shfl_xor_sync(0xffffffffu, s, 1);
    s += __shfl_xor_sync(0xffffffffu, s, 2);
    float mean = s * 0.0625f;
    float dx = y.x - mean, dy = y.y - mean, dz = y.z - mean, dw = y.w - mean;
    float q2 = dx * dx + dy * dy + dz * dz + dw * dw;
    q2 += __shfl_xor_sync(0xffffffffu, q2, 1);
    q2 += __shfl_xor_sync(0xffffffffu, q2, 2);
    float inv = rsqrtf(q2 * 0.0625f + EPS_GN);
    float4 g4 = *(const float4*)&gamma[lane * 4];
    float4 b4 = *(const float4*)&beta[lane * 4];
    float4 r;
    r.x = dx * inv * g4.x + b4.x;
    r.y = dy * inv * g4.y + b4.y;
    r.z = dz * inv * g4.z + b4.z;
    r.w = dw * inv * g4.w + b4.w;
    *(float4*)&out[gw * 128 + lane * 4] = r;
}

// ---------------- launch ---------------------------------------------------
extern "C" void kernel_launch(void* const* d_in, const int* in_sizes, int n_in,
                              void* d_out, int out_size) {
    const float* x    = (const float*)d_in[0];
    const void*  ei   = d_in[1];                 // int32 or int64, detected
    const float* ea   = (const float*)d_in[2];
    const float* Wq   = (const float*)d_in[3];
    const float* bq   = (const float*)d_in[4];
    const float* Wk   = (const float*)d_in[5];
    const float* bk   = (const float*)d_in[6];
    const float* Wv   = (const float*)d_in[7];
    const float* bv   = (const float*)d_in[8];
    const float* We   = (const float*)d_in[9];
    const float* be   = (const float*)d_in[10];
    const float* Wo   = (const float*)d_in[11];
    const float* bo   = (const float*)d_in[12];
    const float* gam  = (const float*)d_in[13];
    const float* bet  = (const float*)d_in[14];
    float*       out  = (float*)d_out;

    // detect edge_index dtype, then CSR build by dst
    k_detect<<<1, 128>>>((const int*)ei);
    k_zero<<<(N_NODES + 255) / 256, 256>>>();
    k_hist<<<800, 256>>>(ei);
    k_scan<<<1, 1024>>>();
    k_scatter<<<800, 256>>>(ei);

    // QKV projections (one launch, z selects output)
    dim3 ggrid((N_NODES + 63) / 64, 2, 3);
    k_gemm_qkv<<<ggrid, 256>>>(x, Wq, bq, Wk, bk, Wv, bv);

    // fused edge attention + online softmax + aggregation
    k_agg<<<(N_NODES * 32 + 511) / 512, 512>>>(ei, ea, We, be);

    // output projection + GroupNorm
    dim3 ogrid((N_NODES + 63) / 64, 2, 1);
    k_gemm_o<<<ogrid, 256>>>(Wo, bo);
    k_gn<<<(N_NODES * 32 + 511) / 512, 512>>>(gam, bet, out);
}

// round 14
// speedup vs baseline: 1.0787x; 1.0787x over previous
#include <cuda_runtime.h>

#define N_NODES 50000
#define D 128
#define NHEAD 8
#define HD 16
#define E_EDGES 800000
#define EDGE_DIM 4
#define EPS_GN 1e-5f
#define SCAN_BLOCKS 49   // ceil(50000 / 1024)

// ---------------- scratch (static device allocations; no cudaMalloc) -------
__device__ float g_q[N_NODES * D];
__device__ float g_k[N_NODES * D];
__device__ float g_v[N_NODES * D];
__device__ float g_agg[N_NODES * D];
__device__ float g_o[N_NODES * D];
__device__ int   g_deg[N_NODES];
__device__ int   g_rowstart[N_NODES + 1];
__device__ int   g_cursor[N_NODES];
__device__ int   g_csr[E_EDGES];
__device__ int   g_blocksum[64];
__device__ int   g_mode64;      // 1 if edge_index is int64, 0 if int32

// index loader: pos in [0, 2E). Handles int32 or int64 storage.
__device__ __forceinline__ int load_idx(const void* ei, int pos, int mode64) {
    long long v;
    if (mode64) v = ((const long long*)ei)[pos];
    else        v = ((const int*)ei)[pos];
    int i = (int)v;
    // clamp for safety: bad index -> wrong answer, not a trap
    return (i < 0) ? 0 : (i >= N_NODES ? N_NODES - 1 : i);
}

// ---------------- dtype detect + zero (fused, one launch) ------------------
// int64 little-endian node ids < 2^31: every odd 32-bit word of src region
// is 0. int32: odd words are random node ids. Block 0 detects via ballot.
__global__ void k_detect_zero(const int* __restrict__ ei_w) {
    int i = blockIdx.x * blockDim.x + threadIdx.x;
    if (i < N_NODES) { g_deg[i] = 0; g_cursor[i] = 0; }
    if (blockIdx.x == 0 && threadIdx.x < 32) {
        int nz = (ei_w[2 * threadIdx.x + 1] != 0) ||
                 (ei_w[2 * (threadIdx.x + 32) + 1] != 0);
        unsigned m = __ballot_sync(0xffffffffu, nz);
        if (threadIdx.x == 0) g_mode64 = (m == 0u) ? 1 : 0;
    }
}

// ---------------- CSR build ------------------------------------------------
__global__ void k_hist(const void* __restrict__ ei) {
    int m64 = g_mode64;
    for (int e = blockIdx.x * blockDim.x + threadIdx.x; e < E_EDGES;
         e += gridDim.x * blockDim.x) {
        int dst = load_idx(ei, E_EDGES + e, m64);
        atomicAdd(&g_deg[dst], 1);
    }
}

// multi-block exclusive scan, phase 1: per-chunk scan + block totals
__global__ void __launch_bounds__(1024) k_scan1() {
    __shared__ int warp_sums[32];
    int tid = threadIdx.x;
    int lane = tid & 31, wrp = tid >> 5;
    int i = blockIdx.x * 1024 + tid;
    int v = (i < N_NODES) ? g_deg[i] : 0;
    int x = v;
    #pragma unroll
    for (int off = 1; off < 32; off *= 2) {
        int y = __shfl_up_sync(0xffffffffu, x, off);
        if (lane >= off) x += y;
    }
    if (lane == 31) warp_sums[wrp] = x;
    __syncthreads();
    if (tid < 32) {
        int w = warp_sums[tid];
        #pragma unroll
        for (int off = 1; off < 32; off *= 2) {
            int y = __shfl_up_sync(0xffffffffu, w, off);
            if (tid >= off) w += y;
        }
        warp_sums[tid] = w;
    }
    __syncthreads();
    int excl = (x - v) + ((wrp > 0) ? warp_sums[wrp - 1] : 0);
    if (i < N_NODES) g_rowstart[i] = excl;       // chunk-local exclusive
    if (tid == 1023) g_blocksum[blockIdx.x] = warp_sums[31];  // block total
}

// phase 2: scan the 49 block totals (one block, 64 threads)
__global__ void k_scan2() {
    __shared__ int ws[2];
    int tid = threadIdx.x;        // 64 threads = 2 warps
    int lane = tid & 31, wrp = tid >> 5;
    int v = (tid < SCAN_BLOCKS) ? g_blocksum[tid] : 0;
    int x = v;
    #pragma unroll
    for (int off = 1; off < 32; off *= 2) {
        int y = __shfl_up_sync(0xffffffffu, x, off);
        if (lane >= off) x += y;
    }
    if (lane == 31) ws[wrp] = x;
    __syncthreads();
    int incl = x + ((wrp == 1) ? ws[0] : 0);
    if (tid < SCAN_BLOCKS) g_blocksum[tid] = incl - v;   // exclusive
    if (tid == SCAN_BLOCKS - 1) g_rowstart[N_NODES] = incl;  // grand total = E
}

// phase 3: add block offsets
__global__ void __launch_bounds__(1024) k_scan3() {
    int i = blockIdx.x * 1024 + threadIdx.x;
    if (i < N_NODES) g_rowstart[i] += g_blocksum[blockIdx.x];
}

__global__ void k_scatter(const void* __restrict__ ei) {
    int m64 = g_mode64;
    for (int e = blockIdx.x * blockDim.x + threadIdx.x; e < E_EDGES;
         e += gridDim.x * blockDim.x) {
        int dst = load_idx(ei, E_EDGES + e, m64);
        int pos = atomicAdd(&g_cursor[dst], 1);
        g_csr[g_rowstart[dst] + pos] = e;
    }
}

// ---------------- fp32 tiled GEMM: C[M,128] = X[M,128] @ W[128,128] + b ----
// BM=64, BN=64, BK=16, 256 threads, each thread 4x4 outputs.
__device__ __forceinline__ void gemm_body(const float* __restrict__ X,
                                          const float* __restrict__ W,
                                          const float* __restrict__ bias,
                                          float* __restrict__ C, int M) {
    __shared__ __align__(16) float xs[16][68];  // [kk][row]
    __shared__ __align__(16) float ws[16][68];  // [kk][col]
    int tid = threadIdx.x;
    int tx = tid & 15, ty = tid >> 4;
    int rowBase = blockIdx.x * 64;
    int colBase = blockIdx.y * 64;

    float acc[4][4];
    #pragma unroll
    for (int i = 0; i < 4; i++)
        #pragma unroll
        for (int j = 0; j < 4; j++) acc[i][j] = 0.f;

    int lr = tid & 3;       // which k-quad of the x row
    int lrow = tid >> 2;    // 0..63
    int wc = (tid & 15) * 4;
    int wk = tid >> 4;

    for (int k0 = 0; k0 < 128; k0 += 16) {
        int gr = rowBase + lrow;
        float4 xv = make_float4(0.f, 0.f, 0.f, 0.f);
        if (gr < M) xv = *(const float4*)&X[gr * 128 + k0 + lr * 4];
        xs[lr * 4 + 0][lrow] = xv.x;
        xs[lr * 4 + 1][lrow] = xv.y;
        xs[lr * 4 + 2][lrow] = xv.z;
        xs[lr * 4 + 3][lrow] = xv.w;

        float4 wv = *(const float4*)&W[(k0 + wk) * 128 + colBase + wc];
        *(float4*)&ws[wk][wc] = wv;
        __syncthreads();

        #pragma unroll
        for (int kk = 0; kk < 16; ++kk) {
            float4 a = *(const float4*)&xs[kk][ty * 4];
            float4 b = *(const float4*)&ws[kk][tx * 4];
            float av[4] = {a.x, a.y, a.z, a.w};
            float bv[4] = {b.x, b.y, b.z, b.w};
            #pragma unroll
            for (int i = 0; i < 4; i++)
                #pragma unroll
                for (int j = 0; j < 4; j++) acc[i][j] += av[i] * bv[j];
        }
        __syncthreads();
    }

    float4 b4 = *(const float4*)&bias[colBase + tx * 4];
    #pragma unroll
    for (int i = 0; i < 4; i++) {
        int r = rowBase + ty * 4 + i;
        if (r < M) {
            float4 ob;
            ob.x = acc[i][0] + b4.x;
            ob.y = acc[i][1] + b4.y;
            ob.z = acc[i][2] + b4.z;
            ob.w = acc[i][3] + b4.w;
            *(float4*)&C[r * 128 + colBase + tx * 4] = ob;
        }
    }
}

// QKV in one launch: blockIdx.z selects (W, b, out)
__global__ void __launch_bounds__(256) k_gemm_qkv(const float* __restrict__ X,
                                                  const float* __restrict__ Wq,
                                                  const float* __restrict__ bq,
                                                  const float* __restrict__ Wk,
                                                  const float* __restrict__ bk,
                                                  const float* __restrict__ Wv,
                                                  const float* __restrict__ bv) {
    const float* W;
    const float* b;
    float* C;
    if (blockIdx.z == 0)      { W = Wq; b = bq; C = g_q; }
    else if (blockIdx.z == 1) { W = Wk; b = bk; C = g_k; }
    else                      { W = Wv; b = bv; C = g_v; }
    gemm_body(X, W, b, C, N_NODES);
}

// O projection: X = g_agg (device global), out = g_o
__global__ void __launch_bounds__(256) k_gemm_o(const float* __restrict__ Wo,
                                                const float* __restrict__ bo) {
    gemm_body(g_agg, Wo, bo, g_o, N_NODES);
}

// ---------------- fused edge logits + online scatter-softmax + aggregation -
// one warp per dst node; lane l owns channels 4l..4l+3 (head = l/4)
__global__ void __launch_bounds__(512) k_agg(const void* __restrict__ ei,
                                             const float* __restrict__ ea,
                                             const float* __restrict__ We,
                                             const float* __restrict__ be) {
    int gw = (blockIdx.x * blockDim.x + threadIdx.x) >> 5;
    int lane = threadIdx.x & 31;
    if (gw >= N_NODES) return;
    int m64 = g_mode64;
    int n = gw;
    int rs = g_rowstart[n];
    int re = g_rowstart[n + 1];
    int h = lane >> 2;

    float4 ql = *(const float4*)&g_q[n * D + lane * 4];
    float w0 = We[0 * NHEAD + h], w1 = We[1 * NHEAD + h];
    float w2 = We[2 * NHEAD + h], w3 = We[3 * NHEAD + h];
    float beh = be[h];

    float m = -1e30f, ssum = 0.f;
    float acc0 = 0.f, acc1 = 0.f, acc2 = 0.f, acc3 = 0.f;

    for (int j = rs; j < re; ++j) {
        int e = g_csr[j];
        int s = load_idx(ei, e, m64);            // src node
        const float4 kv = *(const float4*)&g_k[s * D + lane * 4];
        float p = ql.x * kv.x + ql.y * kv.y + ql.z * kv.z + ql.w * kv.w;
        p += __shfl_xor_sync(0xffffffffu, p, 1);
        p += __shfl_xor_sync(0xffffffffu, p, 2);  // full per-head dot in quad
        float4 ea4 = *(const float4*)&ea[e * 4];
        float logit = p * 0.25f +
                      (ea4.x * w0 + ea4.y * w1 + ea4.z * w2 + ea4.w * w3 + beh);
        float mn = fmaxf(m, logit);
        float f = __expf(m - mn);
        float w = __expf(logit - mn);
        ssum = ssum * f + w;
        const float4 vv = *(const float4*)&g_v[s * D + lane * 4];
        acc0 = acc0 * f + w * vv.x;
        acc1 = acc1 * f + w * vv.y;
        acc2 = acc2 * f + w * vv.z;
        acc3 = acc3 * f + w * vv.w;
        m = mn;
    }
    float inv = 1.0f / fmaxf(ssum, 1e-6f);
    float4 o;
    o.x = acc0 * inv; o.y = acc1 * inv; o.z = acc2 * inv; o.w = acc3 * inv;
    *(float4*)&g_agg[n * D + lane * 4] = o;
}

// ---------------- GroupNorm (8 groups of 16 ch): warp per row --------------
__global__ void __launch_bounds__(512) k_gn(const float* __restrict__ gamma,
                                            const float* __restrict__ beta,
                                            float* __restrict__ out) {
    int gw = (blockIdx.x * blockDim.x + threadIdx.x) >> 5;
    int lane = threadIdx.x & 31;
    if (gw >= N_NODES) return;
    float4 y = *(const float4*)&g_o[gw * 128 + lane * 4];
    float s = y.x + y.y + y.z + y.w;
    s += __shfl_xor_sync(0xffffffffu, s, 1);
    s += __shfl_xor_sync(0xffffffffu, s, 2);
    float mean = s * 0.0625f;
    float dx = y.x - mean, dy = y.y - mean, dz = y.z - mean, dw = y.w - mean;
    float q2 = dx * dx + dy * dy + dz * dz + dw * dw;
    q2 += __shfl_xor_sync(0xffffffffu, q2, 1);
    q2 += __shfl_xor_sync(0xffffffffu, q2, 2);
    float inv = rsqrtf(q2 * 0.0625f + EPS_GN);
    float4 g4 = *(const float4*)&gamma[lane * 4];
    float4 b4 = *(const float4*)&beta[lane * 4];
    float4 r;
    r.x = dx * inv * g4.x + b4.x;
    r.y = dy * inv * g4.y + b4.y;
    r.z = dz * inv * g4.z + b4.z;
    r.w = dw * inv * g4.w + b4.w;
    *(float4*)&out[gw * 128 + lane * 4] = r;
}

// ---------------- launch ---------------------------------------------------
extern "C" void kernel_launch(void* const* d_in, const int* in_sizes, int n_in,
                              void* d_out, int out_size) {
    const float* x    = (const float*)d_in[0];
    const void*  ei   = d_in[1];                 // int32 or int64, detected
    const float* ea   = (const float*)d_in[2];
    const float* Wq   = (const float*)d_in[3];
    const float* bq   = (const float*)d_in[4];
    const float* Wk   = (const float*)d_in[5];
    const float* bk   = (const float*)d_in[6];
    const float* Wv   = (const float*)d_in[7];
    const float* bv   = (const float*)d_in[8];
    const float* We   = (const float*)d_in[9];
    const float* be   = (const float*)d_in[10];
    const float* Wo   = (const float*)d_in[11];
    const float* bo   = (const float*)d_in[12];
    const float* gam  = (const float*)d_in[13];
    const float* bet  = (const float*)d_in[14];
    float*       out  = (float*)d_out;

    // fused dtype detect + counter zero, then CSR build by dst
    k_detect_zero<<<(N_NODES + 255) / 256, 256>>>((const int*)ei);
    k_hist<<<800, 256>>>(ei);
    k_scan1<<<SCAN_BLOCKS, 1024>>>();
    k_scan2<<<1, 64>>>();
    k_scan3<<<SCAN_BLOCKS, 1024>>>();
    k_scatter<<<800, 256>>>(ei);

    // QKV projections (one launch, z selects output)
    dim3 ggrid((N_NODES + 63) / 64, 2, 3);
    k_gemm_qkv<<<ggrid, 256>>>(x, Wq, bq, Wk, bk, Wv, bv);

    // fused edge attention + online softmax + aggregation
    k_agg<<<(N_NODES * 32 + 511) / 512, 512>>>(ei, ea, We, be);

    // output projection + GroupNorm
    dim3 ogrid((N_NODES + 63) / 64, 2, 1);
    k_gemm_o<<<ogrid, 256>>>(Wo, bo);
    k_gn<<<(N_NODES * 32 + 511) / 512, 512>>>(gam, bet, out);
}